// round 9
// baseline (speedup 1.0000x reference)
#include <cuda_runtime.h>
#include <cuda_fp16.h>

#define NB 8
#define CH 64
#define HH 256
#define WW 256
#define PP (HH*WW)   // 65536 pixels per batch

// fp16 scratch: 8-deep NHWC feature ring (8x8MB=64MB) + 2-deep NHWC
// intermediate (2x8MB). Hot working set ~40MB -> L2-resident (126MB L2).
// 8-deep ring keeps the sync-free transpose blocks race-free under PDL
// overlap (distinct batches -> distinct buffers within a replay; replay
// boundary serialized by the non-PDL prologue launch).
__device__ __half g_fN[8][(size_t)PP * CH];
__device__ __half g_first[2][(size_t)PP * CH];

// ---------------------------------------------------------------------------
// Transpose one 64ch x 64px tile of batch n: fp32 NCHW -> fp16 NHWC.
// ---------------------------------------------------------------------------
__device__ __forceinline__ void transpose_tile(const float* __restrict__ feat,
                                               int n, int tile,
                                               float* __restrict__ sm /*64*65*/) {
    const int pbase = tile * 64;
    const int t = threadIdx.x;
    const float* src = feat + (size_t)n * CH * PP;

    const int px4 = (t & 15) * 4;   // pixel offset 0..60
    const int c0  = t >> 4;         // 0..15
    #pragma unroll
    for (int i = 0; i < 4; i++) {
        const int c = c0 + i * 16;
        const float4 v = *(const float4*)(src + (size_t)c * PP + pbase + px4);
        sm[c * 65 + px4 + 0] = v.x;
        sm[c * 65 + px4 + 1] = v.y;
        sm[c * 65 + px4 + 2] = v.z;
        sm[c * 65 + px4 + 3] = v.w;
    }
    __syncthreads();

    __half* dst = g_fN[n & 7];
    const int c8  = t & 7;          // 8-channel chunk
    const int px0 = t >> 3;         // 0..31
    #pragma unroll
    for (int i = 0; i < 2; i++) {
        const int px = px0 + 32 * i;
        __half2 h[4];
        #pragma unroll
        for (int k = 0; k < 4; k++) {
            float2 f = make_float2(sm[(c8 * 8 + 2 * k) * 65 + px],
                                   sm[(c8 * 8 + 2 * k + 1) * 65 + px]);
            h[k] = __float22half2_rn(f);
        }
        ((uint4*)(dst + (size_t)(pbase + px) * 64))[c8] = *(uint4*)h;
    }
}

// ---------------------------------------------------------------------------
// Bilinear helpers (fp32 math, zeros padding; fp16 storage)
// ---------------------------------------------------------------------------
__device__ __forceinline__ void bl_setup(float gx, float gy,
                                         int& x0, int& y0, float& fx, float& fy) {
    float ix = ((gx + 1.0f) * (float)WW - 1.0f) * 0.5f;
    float iy = ((gy + 1.0f) * (float)HH - 1.0f) * 0.5f;
    float fx0 = floorf(ix);
    float fy0 = floorf(iy);
    fx = ix - fx0;
    fy = iy - fy0;
    x0 = (int)fx0;
    y0 = (int)fy0;
}

// Load the 4 corner uint2s (4 fp16 channels each) for one pixel.
// src viewed as [PP][16] uint2 (pixel stride = 64 halves = 16 uint2).
__device__ __forceinline__ void load4_u2(const uint2* __restrict__ src,
                                         int x0, int y0, int c4, uint2* v) {
    const int x1 = x0 + 1, y1 = y0 + 1;
    const bool vx0 = (x0 >= 0) & (x0 < WW);
    const bool vx1 = (x1 >= 0) & (x1 < WW);
    const bool vy0 = (y0 >= 0) & (y0 < HH);
    const bool vy1 = (y1 >= 0) & (y1 < HH);
    const uint2 z = make_uint2(0, 0);
    v[0] = (vx0 & vy0) ? src[(((y0 << 8) + x0) << 4) + c4] : z;
    v[1] = (vx1 & vy0) ? src[(((y0 << 8) + x1) << 4) + c4] : z;
    v[2] = (vx0 & vy1) ? src[(((y1 << 8) + x0) << 4) + c4] : z;
    v[3] = (vx1 & vy1) ? src[(((y1 << 8) + x1) << 4) + c4] : z;
}

// Weighted accumulate of 4 corner uint2s into 4 fp32 channel values.
__device__ __forceinline__ void accum_u2(const uint2* v, float fx, float fy,
                                         float* acc) {
    const float wx1 = fx, wy1 = fy, wx0 = 1.0f - fx, wy0 = 1.0f - fy;
    const float w[4] = {wx0 * wy0, wx1 * wy0, wx0 * wy1, wx1 * wy1};
    #pragma unroll
    for (int j = 0; j < 4; j++) {
        const __half2* h = (const __half2*)&v[j];
        #pragma unroll
        for (int k = 0; k < 2; k++) {
            float2 f = __half22float2(h[k]);
            acc[2 * k]     += f.x * w[j];
            acc[2 * k + 1] += f.y * w[j];
        }
    }
}

__device__ __forceinline__ void store_h4(__half* __restrict__ dst, int p, int c4,
                                         const float* acc) {
    __half2 h[2];
    h[0] = __float22half2_rn(make_float2(acc[0], acc[1]));
    h[1] = __float22half2_rn(make_float2(acc[2], acc[3]));
    ((uint2*)(dst + (size_t)p * 64))[c4] = *(uint2*)h;
}

// ---------------------------------------------------------------------------
// Pass1 block: 64 pixels x 64 channels, 256 threads = 16 lanes/pixel,
// 4 pixels/thread -> 16 independent 8B corner gathers in flight per thread.
// ---------------------------------------------------------------------------
__device__ __forceinline__ void pass1_block(const float* __restrict__ grid,
                                            int n, int blk) {
    const int t   = threadIdx.x;
    const int c4  = t & 15;
    const int pxl = t >> 4;          // 0..15

    int x[4], y[4]; float fx[4], fy[4];
    #pragma unroll
    for (int i = 0; i < 4; i++) {
        const int p = blk * 64 + pxl + 16 * i;
        const float2 g = ((const float2*)grid)[(size_t)n * PP + p];
        bl_setup(g.x, g.y, x[i], y[i], fx[i], fy[i]);
    }

    const uint2* src = (const uint2*)g_fN[n & 7];
    uint2 v[4][4];
    #pragma unroll
    for (int i = 0; i < 4; i++)
        load4_u2(src, x[i], y[i], c4, v[i]);

    float acc[4][4] = {};
    #pragma unroll
    for (int i = 0; i < 4; i++)
        accum_u2(v[i], fx[i], fy[i], acc[i]);

    __half* dst = g_first[n & 1];
    #pragma unroll
    for (int i = 0; i < 4; i++)
        store_h4(dst, blk * 64 + pxl + 16 * i, c4, acc[i]);
}

// ---------------------------------------------------------------------------
// Pass2 block: 64 pixels x 64 channels, 256 threads, 4 pixels/thread;
// smem-staged fp32 NCHW output.
// ---------------------------------------------------------------------------
__device__ __forceinline__ void pass2_block(const float* __restrict__ grid,
                                            float* __restrict__ out,
                                            int n, int blk,
                                            float* __restrict__ smf /*64*65*/) {
    const int t   = threadIdx.x;
    const int c4  = t & 15;
    const int pxl = t >> 4;          // 0..15
    const int p0  = blk * 64;

    int x[4], y[4]; float fx[4], fy[4];
    #pragma unroll
    for (int i = 0; i < 4; i++) {
        const int p = p0 + pxl + 16 * i;
        const float2 g = ((const float2*)grid)[(size_t)n * PP + p];
        bl_setup(g.x, g.y, x[i], y[i], fx[i], fy[i]);
    }

    const uint2* src = (const uint2*)g_first[n & 1];
    uint2 v[4][4];
    #pragma unroll
    for (int i = 0; i < 4; i++)
        load4_u2(src, x[i], y[i], c4, v[i]);

    float acc[4][4] = {};
    #pragma unroll
    for (int i = 0; i < 4; i++)
        accum_u2(v[i], fx[i], fy[i], acc[i]);

    #pragma unroll
    for (int i = 0; i < 4; i++) {
        const int px = pxl + 16 * i;
        #pragma unroll
        for (int k = 0; k < 4; k++)
            smf[(c4 * 4 + k) * 65 + px] = acc[i][k];
    }
    __syncthreads();

    const int w = t >> 5, lane = t & 31;     // 8 warps x 8 channels each
    #pragma unroll
    for (int k = 0; k < 8; k++) {
        const int cc = w * 8 + k;
        const size_t ob = (((size_t)n * CH + cc) << 16) + p0;
        out[ob + lane]      = smf[cc * 65 + lane];
        out[ob + 32 + lane] = smf[cc * 65 + 32 + lane];
    }
}

// ---------------------------------------------------------------------------
// Prologue: transpose batches 0 and 1 (2048 tiles). Launched without PDL.
// ---------------------------------------------------------------------------
__global__ void __launch_bounds__(256, 4)
k_transpose01(const float* __restrict__ feat) {
    cudaTriggerProgrammaticLaunchCompletion();
    __shared__ float sm[64 * 65];
    transpose_tile(feat, blockIdx.x >> 10, blockIdx.x & 1023, sm);
}

// Fused A(m): blocks [0,1024) = transpose batch m+2 (sync-free tail filler);
//             blocks [1024, 3072) = pass1 for batches m and m+1 (synced).
__global__ void __launch_bounds__(256, 4)
k_fusedA(const float* __restrict__ feat, const float* __restrict__ grid, int m) {
    cudaTriggerProgrammaticLaunchCompletion();
    __shared__ float sm[64 * 65];
    if (blockIdx.x < 1024) {
        if (m + 2 < NB)
            transpose_tile(feat, m + 2, blockIdx.x, sm);
    } else {
        cudaGridDependencySynchronize();   // wait predecessor (prologue / B(m-2))
        const int b = blockIdx.x - 1024;
        pass1_block(grid, m + (b >> 10), b & 1023);
    }
}

// Fused B(m): blocks [0,1024) = transpose batch m+3 (sync-free tail filler);
//             blocks [1024, 3072) = pass2 for batches m and m+1 (synced).
__global__ void __launch_bounds__(256, 4)
k_fusedB(const float* __restrict__ feat, const float* __restrict__ grid,
         float* __restrict__ out, int m) {
    cudaTriggerProgrammaticLaunchCompletion();
    __shared__ float sm[64 * 65];
    if (blockIdx.x < 1024) {
        if (m + 3 < NB)
            transpose_tile(feat, m + 3, blockIdx.x, sm);
    } else {
        cudaGridDependencySynchronize();   // wait A(m) (pass1 results)
        const int b = blockIdx.x - 1024;
        pass2_block(grid, out, m + (b >> 10), b & 1023, sm);
    }
}

// ---------------------------------------------------------------------------
static inline void launch_pdl(void* func, dim3 grid, void** args) {
    cudaLaunchConfig_t cfg = {};
    cfg.gridDim = grid;
    cfg.blockDim = dim3(256, 1, 1);
    cfg.dynamicSmemBytes = 0;
    cfg.stream = 0;
    cudaLaunchAttribute attr[1];
    attr[0].id = cudaLaunchAttributeProgrammaticStreamSerialization;
    attr[0].val.programmaticStreamSerializationAllowed = 1;
    cfg.attrs = attr;
    cfg.numAttrs = 1;
    cudaLaunchKernelExC(&cfg, func, args);
}

extern "C" void kernel_launch(void* const* d_in, const int* in_sizes, int n_in,
                              void* d_out, int out_size) {
    const float* feature = (const float*)d_in[0];
    const float* grid    = (const float*)d_in[1];
    float*       out     = (float*)d_out;

    k_transpose01<<<2048, 256>>>(feature);
    for (int m = 0; m < NB; m += 2) {
        {
            void* args[] = {(void*)&feature, (void*)&grid, (void*)&m};
            launch_pdl((void*)k_fusedA, dim3(3072), args);
        }
        {
            void* args[] = {(void*)&feature, (void*)&grid, (void*)&out, (void*)&m};
            launch_pdl((void*)k_fusedB, dim3(3072), args);
        }
    }
}

// round 11
// speedup vs baseline: 1.3805x; 1.3805x over previous
#include <cuda_runtime.h>
#include <cuda_fp16.h>
#include <cstdint>

#define NB 8
#define CH 64
#define HH 256
#define WW 256
#define PP (HH*WW)   // 65536 pixels per batch

// fp16 scratch: 8-deep NHWC feature ring (8x8MB=64MB) + 2-deep NHWC
// intermediate (2x8MB). Hot working set ~40MB -> L2-resident (126MB L2).
__device__ __half g_fN[8][(size_t)PP * CH];
__device__ __half g_first[2][(size_t)PP * CH];

// ---------------------------------------------------------------------------
// cp.async helpers
// ---------------------------------------------------------------------------
__device__ __forceinline__ unsigned int smem_u32(const void* p) {
    return (unsigned int)__cvta_generic_to_shared(p);
}
#define CP_ASYNC16(d, s, sz) \
    asm volatile("cp.async.cg.shared.global [%0], [%1], 16, %2;" \
                 :: "r"(d), "l"(s), "r"(sz))
#define CP_COMMIT() asm volatile("cp.async.commit_group;" ::: "memory")
#define CP_WAIT0()  asm volatile("cp.async.wait_group 0;" ::: "memory")

// ---------------------------------------------------------------------------
// Transpose one 64ch x 64px tile of batch n: fp32 NCHW -> fp16 NHWC.
// Uses 64*65 floats of the shared staging buffer.
// ---------------------------------------------------------------------------
__device__ __forceinline__ void transpose_tile(const float* __restrict__ feat,
                                               int n, int tile,
                                               float* __restrict__ sm /*64*65*/) {
    const int pbase = tile * 64;
    const int t = threadIdx.x;
    const float* src = feat + (size_t)n * CH * PP;

    const int px4 = (t & 15) * 4;   // pixel offset 0..60
    const int c0  = t >> 4;         // 0..15
    #pragma unroll
    for (int i = 0; i < 4; i++) {
        const int c = c0 + i * 16;
        const float4 v = *(const float4*)(src + (size_t)c * PP + pbase + px4);
        sm[c * 65 + px4 + 0] = v.x;
        sm[c * 65 + px4 + 1] = v.y;
        sm[c * 65 + px4 + 2] = v.z;
        sm[c * 65 + px4 + 3] = v.w;
    }
    __syncthreads();

    __half* dst = g_fN[n & 7];
    const int c8  = t & 7;          // 8-channel chunk
    const int px0 = t >> 3;         // 0..31
    #pragma unroll
    for (int i = 0; i < 2; i++) {
        const int px = px0 + 32 * i;
        __half2 h[4];
        #pragma unroll
        for (int k = 0; k < 4; k++) {
            float2 f = make_float2(sm[(c8 * 8 + 2 * k) * 65 + px],
                                   sm[(c8 * 8 + 2 * k + 1) * 65 + px]);
            h[k] = __float22half2_rn(f);
        }
        ((uint4*)(dst + (size_t)(pbase + px) * 64))[c8] = *(uint4*)h;
    }
}

// ---------------------------------------------------------------------------
// Bilinear helpers (fp32 math, zeros padding; fp16 storage)
// ---------------------------------------------------------------------------
__device__ __forceinline__ void bl_setup(float gx, float gy,
                                         int& x0, int& y0, float& fx, float& fy) {
    float ix = ((gx + 1.0f) * (float)WW - 1.0f) * 0.5f;
    float iy = ((gy + 1.0f) * (float)HH - 1.0f) * 0.5f;
    float fx0 = floorf(ix);
    float fy0 = floorf(iy);
    fx = ix - fx0;
    fy = iy - fy0;
    x0 = (int)fx0;
    y0 = (int)fy0;
}

// Stage the 4 corner 16B chunks (channel chunk c8) of pixel local-slot pl
// into smem via cp.async (zero-fill for OOB corners).
// smem layout: byte addr = pl*512 + corner*128 + c8*16  (64px*512B = 32KB).
__device__ __forceinline__ void stage_px(const uint4* __restrict__ src,
                                         unsigned int sbase, int pl, int c8,
                                         int x0, int y0) {
    const int x1 = x0 + 1, y1 = y0 + 1;
    const int v0 = ((x0 >= 0) & (x0 < WW)) ? 16 : 0;
    const int v1 = ((x1 >= 0) & (x1 < WW)) ? 16 : 0;
    const int h0 = ((y0 >= 0) & (y0 < HH)) ? 16 : 0;
    const int h1 = ((y1 >= 0) & (y1 < HH)) ? 16 : 0;
    const int xc0 = min(max(x0, 0), WW - 1), xc1 = min(max(x1, 0), WW - 1);
    const int yc0 = min(max(y0, 0), HH - 1), yc1 = min(max(y1, 0), HH - 1);

    const unsigned int d = sbase + pl * 512 + c8 * 16;
    CP_ASYNC16(d,       &src[(((yc0 << 8) + xc0) << 3) + c8], min(v0, h0));
    CP_ASYNC16(d + 128, &src[(((yc0 << 8) + xc1) << 3) + c8], min(v1, h0));
    CP_ASYNC16(d + 256, &src[(((yc1 << 8) + xc0) << 3) + c8], min(v0, h1));
    CP_ASYNC16(d + 384, &src[(((yc1 << 8) + xc1) << 3) + c8], min(v1, h1));
}

// Accumulate the staged 4 corners of pixel pl (chunk c8) into 8 fp32 channels.
__device__ __forceinline__ void acc_px(const char* __restrict__ sm, int pl, int c8,
                                       float fx, float fy, float* acc /*8*/) {
    const float wx1 = fx, wy1 = fy, wx0 = 1.0f - fx, wy0 = 1.0f - fy;
    const float w[4] = {wx0 * wy0, wx1 * wy0, wx0 * wy1, wx1 * wy1};
    #pragma unroll
    for (int j = 0; j < 4; j++) {
        const uint4 v = *(const uint4*)(sm + pl * 512 + j * 128 + c8 * 16);
        const __half2* h = (const __half2*)&v;
        #pragma unroll
        for (int k = 0; k < 4; k++) {
            float2 f = __half22float2(h[k]);
            acc[2 * k]     += f.x * w[j];
            acc[2 * k + 1] += f.y * w[j];
        }
    }
}

__device__ __forceinline__ void store_h8(__half* __restrict__ dst, int p, int c8,
                                         const float* acc) {
    __half2 h[4];
    #pragma unroll
    for (int k = 0; k < 4; k++)
        h[k] = __float22half2_rn(make_float2(acc[2 * k], acc[2 * k + 1]));
    ((uint4*)(dst + (size_t)p * 64))[c8] = *(uint4*)h;
}

// ---------------------------------------------------------------------------
// Pass1 block: 64 pixels x 64 channels, 256 threads = 8 lanes/pixel,
// 2 pixels/thread. Corners staged via cp.async (no data registers in flight).
// ---------------------------------------------------------------------------
__device__ __forceinline__ void pass1_block(const float* __restrict__ grid,
                                            int n, int blk, char* sstage) {
    const int t   = threadIdx.x;
    const int c8  = t & 7;
    const int pxl = t >> 3;          // 0..31
    const int pA  = blk * 64 + pxl;
    const int pB  = pA + 32;
    const unsigned int sb = smem_u32(sstage);

    const float2 gA = ((const float2*)grid)[(size_t)n * PP + pA];
    const float2 gB = ((const float2*)grid)[(size_t)n * PP + pB];
    int xA, yA, xB, yB; float fxA, fyA, fxB, fyB;
    bl_setup(gA.x, gA.y, xA, yA, fxA, fyA);
    bl_setup(gB.x, gB.y, xB, yB, fxB, fyB);

    const uint4* src = (const uint4*)g_fN[n & 7];
    stage_px(src, sb, pxl,      c8, xA, yA);
    stage_px(src, sb, pxl + 32, c8, xB, yB);
    CP_COMMIT();
    CP_WAIT0();

    float accA[8] = {0}, accB[8] = {0};
    acc_px(sstage, pxl,      c8, fxA, fyA, accA);
    acc_px(sstage, pxl + 32, c8, fxB, fyB, accB);

    __half* dst = g_first[n & 1];
    store_h8(dst, pA, c8, accA);
    store_h8(dst, pB, c8, accB);
}

// ---------------------------------------------------------------------------
// Pass2 block: same gather; then reuse the staging smem as the fp32 NCHW
// output staging tile (sync before overwrite).
// ---------------------------------------------------------------------------
__device__ __forceinline__ void pass2_block(const float* __restrict__ grid,
                                            float* __restrict__ out,
                                            int n, int blk, char* sstage) {
    const int t   = threadIdx.x;
    const int c8  = t & 7;
    const int pxl = t >> 3;          // 0..31
    const int p0  = blk * 64;
    const int pA  = p0 + pxl;
    const int pB  = pA + 32;
    const unsigned int sb = smem_u32(sstage);

    const float2 gA = ((const float2*)grid)[(size_t)n * PP + pA];
    const float2 gB = ((const float2*)grid)[(size_t)n * PP + pB];
    int xA, yA, xB, yB; float fxA, fyA, fxB, fyB;
    bl_setup(gA.x, gA.y, xA, yA, fxA, fyA);
    bl_setup(gB.x, gB.y, xB, yB, fxB, fyB);

    const uint4* src = (const uint4*)g_first[n & 1];
    stage_px(src, sb, pxl,      c8, xA, yA);
    stage_px(src, sb, pxl + 32, c8, xB, yB);
    CP_COMMIT();
    CP_WAIT0();

    float accA[8] = {0}, accB[8] = {0};
    acc_px(sstage, pxl,      c8, fxA, fyA, accA);
    acc_px(sstage, pxl + 32, c8, fxB, fyB, accB);

    __syncthreads();                       // staging reads done block-wide
    float* smf = (float*)sstage;           // reuse as 64x65 fp32 tile
    #pragma unroll
    for (int k = 0; k < 8; k++) {
        smf[(c8 * 8 + k) * 65 + pxl]      = accA[k];
        smf[(c8 * 8 + k) * 65 + pxl + 32] = accB[k];
    }
    __syncthreads();

    const int w = t >> 5, lane = t & 31;   // 8 warps x 8 channels each
    #pragma unroll
    for (int k = 0; k < 8; k++) {
        const int cc = w * 8 + k;
        const size_t ob = (((size_t)n * CH + cc) << 16) + p0;
        out[ob + lane]      = smf[cc * 65 + lane];
        out[ob + 32 + lane] = smf[cc * 65 + 32 + lane];
    }
}

// ---------------------------------------------------------------------------
// Prologue: transpose batches 0 and 1 (2048 tiles). Launched without PDL.
// ---------------------------------------------------------------------------
__global__ void __launch_bounds__(256, 6)
k_transpose01(const float* __restrict__ feat) {
    cudaTriggerProgrammaticLaunchCompletion();
    __shared__ __align__(16) char sraw[32768];
    transpose_tile(feat, blockIdx.x >> 10, blockIdx.x & 1023, (float*)sraw);
}

// Fused A(m): blocks [0,1024) = transpose batch m+2 (sync-free tail filler);
//             blocks [1024, 3072) = pass1 for batches m and m+1 (synced).
__global__ void __launch_bounds__(256, 6)
k_fusedA(const float* __restrict__ feat, const float* __restrict__ grid, int m) {
    cudaTriggerProgrammaticLaunchCompletion();
    __shared__ __align__(16) char sraw[32768];
    if (blockIdx.x < 1024) {
        if (m + 2 < NB)
            transpose_tile(feat, m + 2, blockIdx.x, (float*)sraw);
    } else {
        cudaGridDependencySynchronize();   // wait predecessor (prologue / B(m-2))
        const int b = blockIdx.x - 1024;
        pass1_block(grid, m + (b >> 10), b & 1023, sraw);
    }
}

// Fused B(m): blocks [0,1024) = transpose batch m+3 (sync-free tail filler);
//             blocks [1024, 3072) = pass2 for batches m and m+1 (synced).
__global__ void __launch_bounds__(256, 6)
k_fusedB(const float* __restrict__ feat, const float* __restrict__ grid,
         float* __restrict__ out, int m) {
    cudaTriggerProgrammaticLaunchCompletion();
    __shared__ __align__(16) char sraw[32768];
    if (blockIdx.x < 1024) {
        if (m + 3 < NB)
            transpose_tile(feat, m + 3, blockIdx.x, (float*)sraw);
    } else {
        cudaGridDependencySynchronize();   // wait A(m) (pass1 results)
        const int b = blockIdx.x - 1024;
        pass2_block(grid, out, m + (b >> 10), b & 1023, sraw);
    }
}

// ---------------------------------------------------------------------------
static inline void launch_pdl(void* func, dim3 grid, void** args) {
    cudaLaunchConfig_t cfg = {};
    cfg.gridDim = grid;
    cfg.blockDim = dim3(256, 1, 1);
    cfg.dynamicSmemBytes = 0;
    cfg.stream = 0;
    cudaLaunchAttribute attr[1];
    attr[0].id = cudaLaunchAttributeProgrammaticStreamSerialization;
    attr[0].val.programmaticStreamSerializationAllowed = 1;
    cfg.attrs = attr;
    cfg.numAttrs = 1;
    cudaLaunchKernelExC(&cfg, func, args);
}

extern "C" void kernel_launch(void* const* d_in, const int* in_sizes, int n_in,
                              void* d_out, int out_size) {
    const float* feature = (const float*)d_in[0];
    const float* grid    = (const float*)d_in[1];
    float*       out     = (float*)d_out;

    k_transpose01<<<2048, 256>>>(feature);
    for (int m = 0; m < NB; m += 2) {
        {
            void* args[] = {(void*)&feature, (void*)&grid, (void*)&m};
            launch_pdl((void*)k_fusedA, dim3(3072), args);
        }
        {
            void* args[] = {(void*)&feature, (void*)&grid, (void*)&out, (void*)&m};
            launch_pdl((void*)k_fusedB, dim3(3072), args);
        }
    }
}

// round 12
// speedup vs baseline: 1.4146x; 1.0247x over previous
#include <cuda_runtime.h>
#include <cuda_fp16.h>
#include <cstdint>

#define NB 8
#define CH 64
#define HH 256
#define WW 256
#define PP (HH*WW)   // 65536 pixels per batch

// fp16 scratch: 8-deep NHWC feature ring (8x8MB=64MB) + 2-deep NHWC
// intermediate (2x8MB). Hot working set ~40MB -> L2-resident (126MB L2).
__device__ __half g_fN[8][(size_t)PP * CH];
__device__ __half g_first[2][(size_t)PP * CH];

// ---------------------------------------------------------------------------
// Transpose one 64ch x 64px tile of batch n: fp32 NCHW -> fp16 NHWC.
// ---------------------------------------------------------------------------
__device__ __forceinline__ void transpose_tile(const float* __restrict__ feat,
                                               int n, int tile,
                                               float* __restrict__ sm /*64*65*/) {
    const int pbase = tile * 64;
    const int t = threadIdx.x;
    const float* src = feat + (size_t)n * CH * PP;

    const int px4 = (t & 15) * 4;   // pixel offset 0..60
    const int c0  = t >> 4;         // 0..15
    #pragma unroll
    for (int i = 0; i < 4; i++) {
        const int c = c0 + i * 16;
        const float4 v = *(const float4*)(src + (size_t)c * PP + pbase + px4);
        sm[c * 65 + px4 + 0] = v.x;
        sm[c * 65 + px4 + 1] = v.y;
        sm[c * 65 + px4 + 2] = v.z;
        sm[c * 65 + px4 + 3] = v.w;
    }
    __syncthreads();

    __half* dst = g_fN[n & 7];
    const int c8  = t & 7;          // 8-channel chunk
    const int px0 = t >> 3;         // 0..31
    #pragma unroll
    for (int i = 0; i < 2; i++) {
        const int px = px0 + 32 * i;
        __half2 h[4];
        #pragma unroll
        for (int k = 0; k < 4; k++) {
            float2 f = make_float2(sm[(c8 * 8 + 2 * k) * 65 + px],
                                   sm[(c8 * 8 + 2 * k + 1) * 65 + px]);
            h[k] = __float22half2_rn(f);
        }
        ((uint4*)(dst + (size_t)(pbase + px) * 64))[c8] = *(uint4*)h;
    }
}

// ---------------------------------------------------------------------------
// Bilinear helpers (fp32 math, zeros padding; fp16 storage)
// ---------------------------------------------------------------------------
__device__ __forceinline__ void bl_setup(float gx, float gy,
                                         int& x0, int& y0, float& fx, float& fy) {
    float ix = ((gx + 1.0f) * (float)WW - 1.0f) * 0.5f;
    float iy = ((gy + 1.0f) * (float)HH - 1.0f) * 0.5f;
    float fx0 = floorf(ix);
    float fy0 = floorf(iy);
    fx = ix - fx0;
    fy = iy - fy0;
    x0 = (int)fx0;
    y0 = (int)fy0;
}

// Load the 4 corner uint4s (8 fp16 channels each) for one pixel.
__device__ __forceinline__ void load4(const uint4* __restrict__ src,
                                      int x0, int y0, int c8, uint4* v) {
    const int x1 = x0 + 1, y1 = y0 + 1;
    const bool vx0 = (x0 >= 0) & (x0 < WW);
    const bool vx1 = (x1 >= 0) & (x1 < WW);
    const bool vy0 = (y0 >= 0) & (y0 < HH);
    const bool vy1 = (y1 >= 0) & (y1 < HH);
    const uint4 z = make_uint4(0, 0, 0, 0);
    v[0] = (vx0 & vy0) ? src[(((y0 << 8) + x0) << 3) + c8] : z;
    v[1] = (vx1 & vy0) ? src[(((y0 << 8) + x1) << 3) + c8] : z;
    v[2] = (vx0 & vy1) ? src[(((y1 << 8) + x0) << 3) + c8] : z;
    v[3] = (vx1 & vy1) ? src[(((y1 << 8) + x1) << 3) + c8] : z;
}

// Weighted accumulate of 4 corner uint4s into 8 fp32 channel values.
__device__ __forceinline__ void accum(const uint4* v, float fx, float fy,
                                      float* acc) {
    const float wx1 = fx, wy1 = fy, wx0 = 1.0f - fx, wy0 = 1.0f - fy;
    const float w[4] = {wx0 * wy0, wx1 * wy0, wx0 * wy1, wx1 * wy1};
    #pragma unroll
    for (int j = 0; j < 4; j++) {
        const __half2* h = (const __half2*)&v[j];
        #pragma unroll
        for (int k = 0; k < 4; k++) {
            float2 f = __half22float2(h[k]);
            acc[2 * k]     += f.x * w[j];
            acc[2 * k + 1] += f.y * w[j];
        }
    }
}

__device__ __forceinline__ void store_h8(__half* __restrict__ dst, int p, int c8,
                                         const float* acc) {
    __half2 h[4];
    #pragma unroll
    for (int k = 0; k < 4; k++)
        h[k] = __float22half2_rn(make_float2(acc[2 * k], acc[2 * k + 1]));
    ((uint4*)(dst + (size_t)p * 64))[c8] = *(uint4*)h;
}

// ---------------------------------------------------------------------------
// Pass1 block: 64 pixels x 64 channels, 256 threads, 2 pixels/thread.
// ---------------------------------------------------------------------------
__device__ __forceinline__ void pass1_block(const float* __restrict__ grid,
                                            int n, int blk) {
    const int t  = threadIdx.x;
    const int c8 = t & 7;
    const int px = t >> 3;
    const int pA = blk * 64 + px;
    const int pB = pA + 32;

    const float2 gA = ((const float2*)grid)[(size_t)n * PP + pA];
    const float2 gB = ((const float2*)grid)[(size_t)n * PP + pB];
    int xA, yA, xB, yB; float fxA, fyA, fxB, fyB;
    bl_setup(gA.x, gA.y, xA, yA, fxA, fyA);
    bl_setup(gB.x, gB.y, xB, yB, fxB, fyB);

    const uint4* src = (const uint4*)g_fN[n & 7];
    uint4 va[4], vb[4];
    load4(src, xA, yA, c8, va);
    load4(src, xB, yB, c8, vb);

    float accA[8] = {0}, accB[8] = {0};
    accum(va, fxA, fyA, accA);
    accum(vb, fxB, fyB, accB);

    __half* dst = g_first[n & 1];
    store_h8(dst, pA, c8, accA);
    store_h8(dst, pB, c8, accB);
}

// ---------------------------------------------------------------------------
// Pass2 block: 64 pixels x 64 channels, 256 threads; smem-staged fp32 NCHW out.
// ---------------------------------------------------------------------------
__device__ __forceinline__ void pass2_block(const float* __restrict__ grid,
                                            float* __restrict__ out,
                                            int n, int blk,
                                            float* __restrict__ smf /*64*65*/) {
    const int t  = threadIdx.x;
    const int c8 = t & 7;
    const int px = t >> 3;
    const int p0 = blk * 64;
    const int pA = p0 + px;
    const int pB = pA + 32;

    const float2 gA = ((const float2*)grid)[(size_t)n * PP + pA];
    const float2 gB = ((const float2*)grid)[(size_t)n * PP + pB];
    int xA, yA, xB, yB; float fxA, fyA, fxB, fyB;
    bl_setup(gA.x, gA.y, xA, yA, fxA, fyA);
    bl_setup(gB.x, gB.y, xB, yB, fxB, fyB);

    const uint4* src = (const uint4*)g_first[n & 1];
    uint4 va[4], vb[4];
    load4(src, xA, yA, c8, va);
    load4(src, xB, yB, c8, vb);

    float accA[8] = {0}, accB[8] = {0};
    accum(va, fxA, fyA, accA);
    accum(vb, fxB, fyB, accB);

    #pragma unroll
    for (int k = 0; k < 8; k++) {
        smf[(c8 * 8 + k) * 65 + px]      = accA[k];
        smf[(c8 * 8 + k) * 65 + px + 32] = accB[k];
    }
    __syncthreads();

    const int w = t >> 5, lane = t & 31;     // 8 warps x 8 channels each
    #pragma unroll
    for (int k = 0; k < 8; k++) {
        const int cc = w * 8 + k;
        const size_t ob = (((size_t)n * CH + cc) << 16) + p0;
        out[ob + lane]      = smf[cc * 65 + lane];
        out[ob + 32 + lane] = smf[cc * 65 + 32 + lane];
    }
}

// ---------------------------------------------------------------------------
// Prologue: transpose batches 0 and 1 (2048 tiles). Normal launch.
// ---------------------------------------------------------------------------
__global__ void __launch_bounds__(256, 4)
k_transpose01(const float* __restrict__ feat) {
    cudaTriggerProgrammaticLaunchCompletion();
    __shared__ float sm[64 * 65];
    transpose_tile(feat, blockIdx.x >> 10, blockIdx.x & 1023, sm);
}

// Step i (i = 0..8):
//   blocks [0,1024):    transpose(i+2) if i+2<NB  (sync-free tail filler)
//   blocks [1024,2048): pass1(i)   if i<NB        (grid-dep synced)
//   blocks [2048,3072): pass2(i-1) if i>=1        (grid-dep synced)
// Every launch carries an equal DRAM-read / L2-gather / DRAM-write mix.
__global__ void __launch_bounds__(256, 4)
k_step(const float* __restrict__ feat, const float* __restrict__ grid,
       float* __restrict__ out, int i) {
    cudaTriggerProgrammaticLaunchCompletion();
    __shared__ float sm[64 * 65];
    const int b = blockIdx.x;
    if (b < 1024) {
        if (i + 2 < NB)
            transpose_tile(feat, i + 2, b, sm);
    } else if (b < 2048) {
        if (i < NB) {
            cudaGridDependencySynchronize();   // transpose(i) & ring safety
            pass1_block(grid, i, b - 1024);
        }
    } else {
        if (i >= 1) {
            cudaGridDependencySynchronize();   // pass1(i-1) results
            pass2_block(grid, out, i - 1, b - 2048, sm);
        }
    }
}

// ---------------------------------------------------------------------------
static inline void launch_pdl(void* func, dim3 grid, void** args) {
    cudaLaunchConfig_t cfg = {};
    cfg.gridDim = grid;
    cfg.blockDim = dim3(256, 1, 1);
    cfg.dynamicSmemBytes = 0;
    cfg.stream = 0;
    cudaLaunchAttribute attr[1];
    attr[0].id = cudaLaunchAttributeProgrammaticStreamSerialization;
    attr[0].val.programmaticStreamSerializationAllowed = 1;
    cfg.attrs = attr;
    cfg.numAttrs = 1;
    cudaLaunchKernelExC(&cfg, func, args);
}

extern "C" void kernel_launch(void* const* d_in, const int* in_sizes, int n_in,
                              void* d_out, int out_size) {
    const float* feature = (const float*)d_in[0];
    const float* grid    = (const float*)d_in[1];
    float*       out     = (float*)d_out;

    k_transpose01<<<2048, 256>>>(feature);
    for (int i = 0; i <= NB; i++) {
        void* args[] = {(void*)&feature, (void*)&grid, (void*)&out, (void*)&i};
        launch_pdl((void*)k_step, dim3(3072), args);
    }
}

// round 15
// speedup vs baseline: 1.5304x; 1.0819x over previous
#include <cuda_runtime.h>
#include <cuda_fp16.h>
#include <cstdint>

#define NB 8
#define CH 64
#define HH 256
#define WW 256
#define PP (HH*WW)   // 65536 pixels per batch

// fp16 scratch: 8-deep NHWC feature ring (8x8MB=64MB) + 2-deep NHWC
// intermediate (2x8MB). Hot working set ~40MB -> L2-resident (126MB L2).
__device__ __half g_fN[8][(size_t)PP * CH];
__device__ __half g_first[2][(size_t)PP * CH];

// ---------------------------------------------------------------------------
// Transpose one 64ch x 64px tile of batch n: fp32 NCHW -> fp16 NHWC.
// ---------------------------------------------------------------------------
__device__ __forceinline__ void transpose_tile(const float* __restrict__ feat,
                                               int n, int tile,
                                               float* __restrict__ sm /*64*65*/) {
    const int pbase = tile * 64;
    const int t = threadIdx.x;
    const float* src = feat + (size_t)n * CH * PP;

    const int px4 = (t & 15) * 4;   // pixel offset 0..60
    const int c0  = t >> 4;         // 0..15
    #pragma unroll
    for (int i = 0; i < 4; i++) {
        const int c = c0 + i * 16;
        const float4 v = *(const float4*)(src + (size_t)c * PP + pbase + px4);
        sm[c * 65 + px4 + 0] = v.x;
        sm[c * 65 + px4 + 1] = v.y;
        sm[c * 65 + px4 + 2] = v.z;
        sm[c * 65 + px4 + 3] = v.w;
    }
    __syncthreads();

    __half* dst = g_fN[n & 7];
    const int c8  = t & 7;          // 8-channel chunk
    const int px0 = t >> 3;         // 0..31
    #pragma unroll
    for (int i = 0; i < 2; i++) {
        const int px = px0 + 32 * i;
        __half2 h[4];
        #pragma unroll
        for (int k = 0; k < 4; k++) {
            float2 f = make_float2(sm[(c8 * 8 + 2 * k) * 65 + px],
                                   sm[(c8 * 8 + 2 * k + 1) * 65 + px]);
            h[k] = __float22half2_rn(f);
        }
        ((uint4*)(dst + (size_t)(pbase + px) * 64))[c8] = *(uint4*)h;
    }
}

// ---------------------------------------------------------------------------
// Bilinear helpers (fp32 math; zeros padding folded into weights)
// ---------------------------------------------------------------------------
__device__ __forceinline__ void bl_setup(float gx, float gy,
                                         int& x0, int& y0, float& fx, float& fy) {
    float ix = ((gx + 1.0f) * (float)WW - 1.0f) * 0.5f;
    float iy = ((gy + 1.0f) * (float)HH - 1.0f) * 0.5f;
    float fx0 = floorf(ix);
    float fy0 = floorf(iy);
    fx = ix - fx0;
    fy = iy - fy0;
    x0 = (int)fx0;
    y0 = (int)fy0;
}

// Unconditional loads from clamped (always in-bounds) corner addresses.
__device__ __forceinline__ void load4(const uint4* __restrict__ src,
                                      int x0, int y0, int c8, uint4* v) {
    const int xc0 = min(max(x0, 0), WW - 1);
    const int xc1 = min(x0 + 1, WW - 1);       // x0+1 >= 0 always
    const int yc0 = min(max(y0, 0), HH - 1);
    const int yc1 = min(y0 + 1, HH - 1);
    v[0] = src[(((yc0 << 8) + xc0) << 3) + c8];
    v[1] = src[(((yc0 << 8) + xc1) << 3) + c8];
    v[2] = src[(((yc1 << 8) + xc0) << 3) + c8];
    v[3] = src[(((yc1 << 8) + xc1) << 3) + c8];
}

// Bilinear weights with validity folded in (invalid corner -> weight 0,
// exactly matching padding_mode='zeros').
__device__ __forceinline__ void bl_weights(int x0, int y0, float fx, float fy,
                                           float* w /*4*/) {
    const float vx0 = (x0 >= 0) ? 1.0f : 0.0f;            // x0 <= 255 always
    const float vx1 = (x0 + 1 < WW) ? 1.0f : 0.0f;        // x1 >= 0 always
    const float vy0 = (y0 >= 0) ? 1.0f : 0.0f;
    const float vy1 = (y0 + 1 < HH) ? 1.0f : 0.0f;
    const float ax0 = (1.0f - fx) * vx0, ax1 = fx * vx1;
    const float ay0 = (1.0f - fy) * vy0, ay1 = fy * vy1;
    w[0] = ax0 * ay0; w[1] = ax1 * ay0; w[2] = ax0 * ay1; w[3] = ax1 * ay1;
}

// Weighted accumulate of 4 corner uint4s into 8 fp32 channel values.
__device__ __forceinline__ void accum(const uint4* v, const float* w,
                                      float* acc) {
    #pragma unroll
    for (int j = 0; j < 4; j++) {
        const __half2* h = (const __half2*)&v[j];
        #pragma unroll
        for (int k = 0; k < 4; k++) {
            float2 f = __half22float2(h[k]);
            acc[2 * k]     += f.x * w[j];
            acc[2 * k + 1] += f.y * w[j];
        }
    }
}

__device__ __forceinline__ void store_h8(__half* __restrict__ dst, int p, int c8,
                                         const float* acc) {
    __half2 h[4];
    #pragma unroll
    for (int k = 0; k < 4; k++)
        h[k] = __float22half2_rn(make_float2(acc[2 * k], acc[2 * k + 1]));
    ((uint4*)(dst + (size_t)p * 64))[c8] = *(uint4*)h;
}

// ---------------------------------------------------------------------------
// Pass1 block: 64 pixels x 64 channels, 256 threads, 2 pixels/thread.
// ---------------------------------------------------------------------------
__device__ __forceinline__ void pass1_block(const float* __restrict__ grid,
                                            int n, int blk) {
    const int t  = threadIdx.x;
    const int c8 = t & 7;
    const int px = t >> 3;
    const int pA = blk * 64 + px;
    const int pB = pA + 32;

    const float2 gA = ((const float2*)grid)[(size_t)n * PP + pA];
    const float2 gB = ((const float2*)grid)[(size_t)n * PP + pB];
    int xA, yA, xB, yB; float fxA, fyA, fxB, fyB;
    bl_setup(gA.x, gA.y, xA, yA, fxA, fyA);
    bl_setup(gB.x, gB.y, xB, yB, fxB, fyB);

    const uint4* src = (const uint4*)g_fN[n & 7];
    uint4 va[4], vb[4];
    load4(src, xA, yA, c8, va);
    load4(src, xB, yB, c8, vb);

    float wA[4], wB[4];
    bl_weights(xA, yA, fxA, fyA, wA);
    bl_weights(xB, yB, fxB, fyB, wB);

    float accA[8] = {0}, accB[8] = {0};
    accum(va, wA, accA);
    accum(vb, wB, accB);

    __half* dst = g_first[n & 1];
    store_h8(dst, pA, c8, accA);
    store_h8(dst, pB, c8, accB);
}

// ---------------------------------------------------------------------------
// Pass2 block: 64 pixels x 64 channels, 256 threads; smem-staged fp32 NCHW out.
// ---------------------------------------------------------------------------
__device__ __forceinline__ void pass2_block(const float* __restrict__ grid,
                                            float* __restrict__ out,
                                            int n, int blk,
                                            float* __restrict__ smf /*64*65*/) {
    const int t  = threadIdx.x;
    const int c8 = t & 7;
    const int px = t >> 3;
    const int p0 = blk * 64;
    const int pA = p0 + px;
    const int pB = pA + 32;

    const float2 gA = ((const float2*)grid)[(size_t)n * PP + pA];
    const float2 gB = ((const float2*)grid)[(size_t)n * PP + pB];
    int xA, yA, xB, yB; float fxA, fyA, fxB, fyB;
    bl_setup(gA.x, gA.y, xA, yA, fxA, fyA);
    bl_setup(gB.x, gB.y, xB, yB, fxB, fyB);

    const uint4* src = (const uint4*)g_first[n & 1];
    uint4 va[4], vb[4];
    load4(src, xA, yA, c8, va);
    load4(src, xB, yB, c8, vb);

    float wA[4], wB[4];
    bl_weights(xA, yA, fxA, fyA, wA);
    bl_weights(xB, yB, fxB, fyB, wB);

    float accA[8] = {0}, accB[8] = {0};
    accum(va, wA, accA);
    accum(vb, wB, accB);

    #pragma unroll
    for (int k = 0; k < 8; k++) {
        smf[(c8 * 8 + k) * 65 + px]      = accA[k];
        smf[(c8 * 8 + k) * 65 + px + 32] = accB[k];
    }
    __syncthreads();

    const int w = t >> 5, lane = t & 31;     // 8 warps x 8 channels each
    #pragma unroll
    for (int k = 0; k < 8; k++) {
        const int cc = w * 8 + k;
        const size_t ob = (((size_t)n * CH + cc) << 16) + p0;
        out[ob + lane]      = smf[cc * 65 + lane];
        out[ob + 32 + lane] = smf[cc * 65 + 32 + lane];
    }
}

// ---------------------------------------------------------------------------
// Prologue: transpose batches 0 and 1 (2048 tiles). Launched without PDL.
// ---------------------------------------------------------------------------
__global__ void __launch_bounds__(256, 6)
k_transpose01(const float* __restrict__ feat) {
    cudaTriggerProgrammaticLaunchCompletion();
    __shared__ float sm[64 * 65];
    transpose_tile(feat, blockIdx.x >> 10, blockIdx.x & 1023, sm);
}

// Fused A(m): blocks [0,1024) = transpose batch m+2 (sync-free tail filler);
//             blocks [1024, 3072) = pass1 for batches m and m+1 (synced).
__global__ void __launch_bounds__(256, 6)
k_fusedA(const float* __restrict__ feat, const float* __restrict__ grid, int m) {
    cudaTriggerProgrammaticLaunchCompletion();
    __shared__ float sm[64 * 65];
    if (blockIdx.x < 1024) {
        if (m + 2 < NB)
            transpose_tile(feat, m + 2, blockIdx.x, sm);
    } else {
        cudaGridDependencySynchronize();   // wait predecessor (prologue / B(m-2))
        const int b = blockIdx.x - 1024;
        pass1_block(grid, m + (b >> 10), b & 1023);
    }
}

// Fused B(m): blocks [0,1024) = transpose batch m+3 (sync-free tail filler);
//             blocks [1024, 3072) = pass2 for batches m and m+1 (synced).
__global__ void __launch_bounds__(256, 6)
k_fusedB(const float* __restrict__ feat, const float* __restrict__ grid,
         float* __restrict__ out, int m) {
    cudaTriggerProgrammaticLaunchCompletion();
    __shared__ float sm[64 * 65];
    if (blockIdx.x < 1024) {
        if (m + 3 < NB)
            transpose_tile(feat, m + 3, blockIdx.x, sm);
    } else {
        cudaGridDependencySynchronize();   // wait A(m) (pass1 results)
        const int b = blockIdx.x - 1024;
        pass2_block(grid, out, m + (b >> 10), b & 1023, sm);
    }
}

// ---------------------------------------------------------------------------
static inline void launch_pdl(void* func, dim3 grid, void** args) {
    cudaLaunchConfig_t cfg = {};
    cfg.gridDim = grid;
    cfg.blockDim = dim3(256, 1, 1);
    cfg.dynamicSmemBytes = 0;
    cfg.stream = 0;
    cudaLaunchAttribute attr[1];
    attr[0].id = cudaLaunchAttributeProgrammaticStreamSerialization;
    attr[0].val.programmaticStreamSerializationAllowed = 1;
    cfg.attrs = attr;
    cfg.numAttrs = 1;
    cudaLaunchKernelExC(&cfg, func, args);
}

extern "C" void kernel_launch(void* const* d_in, const int* in_sizes, int n_in,
                              void* d_out, int out_size) {
    const float* feature = (const float*)d_in[0];
    const float* grid    = (const float*)d_in[1];
    float*       out     = (float*)d_out;

    k_transpose01<<<2048, 256>>>(feature);
    for (int m = 0; m < NB; m += 2) {
        {
            void* args[] = {(void*)&feature, (void*)&grid, (void*)&m};
            launch_pdl((void*)k_fusedA, dim3(3072), args);
        }
        {
            void* args[] = {(void*)&feature, (void*)&grid, (void*)&out, (void*)&m};
            launch_pdl((void*)k_fusedB, dim3(3072), args);
        }
    }
}